// round 11
// baseline (speedup 1.0000x reference)
#include <cuda_runtime.h>
#include <cstdint>

#define BATCH 512
#define SEQ   512
#define OBS   103
#define HID   512
#define INP   105            // OBS + 2 fed-back pos
#define KTOT  617            // INP + HID
#define GAT   2048           // 4*HID
#define NBLK  128
#define NTHR  512
#define CLUS  8
#define PITCHD 68            // dup'd smem k-row pitch (64 dup floats + pad, 16B-aligned)
#define OFF_H (BATCH*SEQ*2)
#define OFF_C (OFF_H + BATCH*HID)
#define SA_FLOATS (KTOT*PITCHD)       // 41956
#define SMEM_FLOATS (SA_FLOATS + 2048 + 2048 + 256 + 64)
#define SMEM_BYTES  (SMEM_FLOATS*4)   // ~185.6 KB

typedef unsigned long long ull;

// ---- static device scratch (no allocation allowed) ----
__device__ __align__(16) float g_Wt[KTOT*GAT];   // k-major, gate-interleaved cols
__device__ __align__(16) float g_bias[GAT];      // b_ih+b_hh, permuted
__device__ __align__(16) float g_W1t[HID*64];    // layer1 weights, k-major
__device__ __align__(16) float g_W2t[64*16];     // layer2 weights, k-major
__device__ __align__(16) float g_hbuf[2][BATCH*HID];
__device__ __align__(16) float g_y[BATCH*2];

// ---- packed f32x2 helpers ----
__device__ __forceinline__ ull pack2(float lo, float hi) {
    ull r; asm("mov.b64 %0, {%1, %2};" : "=l"(r) : "f"(lo), "f"(hi)); return r;
}
__device__ __forceinline__ float2 unpack2(ull v) {
    float lo, hi; asm("mov.b64 {%0, %1}, %2;" : "=f"(lo), "=f"(hi) : "l"(v));
    return make_float2(lo, hi);
}
__device__ __forceinline__ void fma2(ull &d, ull a, ull b) {
    asm("fma.rn.f32x2 %0, %1, %2, %0;" : "+l"(d) : "l"(a), "l"(b));
}

__device__ __forceinline__ float sigm(float x) { return 1.f / (1.f + __expf(-x)); }
__device__ __forceinline__ float tanh_(float x) {
    x = fminf(15.f, fmaxf(-15.f, x));
    float e = __expf(-2.f * x);
    return (1.f - e) / (1.f + e);
}

// ---- cluster barrier: orders global (L2) h/y writes within the 8-CTA cluster ----
__device__ __forceinline__ void cluster_sync_() {
    asm volatile("barrier.cluster.arrive.aligned;" ::: "memory");
    asm volatile("barrier.cluster.wait.aligned;" ::: "memory");
}

// ---- precompute: permuted transpose of W, combined bias, state init ----
__global__ void precompute_kernel(const float* __restrict__ W_ih,
                                  const float* __restrict__ W_hh,
                                  const float* __restrict__ b_ih,
                                  const float* __restrict__ b_hh,
                                  const float* __restrict__ hidden,
                                  const float* __restrict__ pos,
                                  const float* __restrict__ W1,
                                  const float* __restrict__ W2) {
    const int stride = gridDim.x * blockDim.x;
    const int i0 = blockIdx.x * blockDim.x + threadIdx.x;
    // Wt[k][col]; col = ubp*256 + ul*4 + g  <->  original row r = g*HID + ubp*64 + ul
    for (int idx = i0; idx < KTOT * GAT; idx += stride) {
        int k = idx >> 11, col = idx & 2047;
        int ubp = col >> 8, rem = col & 255, ul = rem >> 2, g = rem & 3;
        int r = g * HID + ubp * 64 + ul;
        g_Wt[idx] = (k < INP) ? W_ih[r * INP + k] : W_hh[r * HID + (k - INP)];
    }
    for (int col = i0; col < GAT; col += stride) {
        int ubp = col >> 8, rem = col & 255, ul = rem >> 2, g = rem & 3;
        int r = g * HID + ubp * 64 + ul;
        g_bias[col] = b_ih[r] + b_hh[r];
    }
    for (int idx = i0; idx < HID * 64; idx += stride) {
        int k = idx >> 6, u1 = idx & 63;
        g_W1t[idx] = W1[u1 * HID + k];
    }
    for (int idx = i0; idx < 64 * 16; idx += stride) {
        int k = idx >> 4, u2 = idx & 15;
        g_W2t[idx] = W2[u2 * 64 + k];
    }
    for (int idx = i0; idx < BATCH * HID; idx += stride) g_hbuf[0][idx] = hidden[idx];
    for (int idx = i0; idx < BATCH * 2; idx += stride)
        g_y[idx] = pos[(idx >> 1) * SEQ * 2 + (idx & 1)];   // pos[:,0,:]
}

// ---- persistent LSTM kernel: 16 independent 8-CTA clusters ----
__global__ void __launch_bounds__(NTHR, 1) __cluster_dims__(CLUS, 1, 1)
lstm_persistent(const float* __restrict__ x,
                const float* __restrict__ cell,
                const float* __restrict__ b1,
                const float* __restrict__ b2,
                const float* __restrict__ W3, const float* __restrict__ b3,
                float* __restrict__ out) {
    extern __shared__ float sm[];
    float* sa    = sm;                     // staged input DUPLICATED, [KTOT][PITCHD]
    float* hbufS = sm + SA_FLOATS;         // MLP h, transposed [512 k][4 rows]
    float* p1s   = hbufS + 2048;           // layer1 partials [8 ks][4 r][64 u1]
    float* y1s   = p1s + 2048;             // 4*64
    float* y2s   = y1s + 256;              // 4*16

    const int tid  = threadIdx.x;
    const int lane = tid & 31;
    const int wid  = tid >> 5;             // 0..15
    const int bt = blockIdx.x >> 3, ct = blockIdx.x & 7;   // ct == cluster rank
    const int tx = tid & 63, ty = tid >> 6;   // tx: unit, ty: batch group
    const int colbase = ct * 256 + tx * 4;    // one unit = 4 interleaved gates
    const int rowbase = bt * 32 + ty * 4;
    const int u       = ct * 64 + tx;         // global hidden unit
    const int mrowb   = blockIdx.x * 4;       // MLP rows (inside this cluster's bt)

    const float4 bA = *(const float4*)(g_bias + colbase);

    // cell state in registers: 4 batch rows x 1 unit
    float c[4];
#pragma unroll
    for (int b = 0; b < 4; b++) c[b] = cell[(size_t)(rowbase + b) * HID + u];

    // ---------- prologue: stage step-0 input (duplicated pairs) ----------
    {
#pragma unroll
        for (int i = 0; i < 2; i++) {
            int b = wid * 2 + i;
            int row = bt * 32 + b;
            const float* xr = x + (size_t)row * SEQ * OBS;
            for (int k = lane; k < OBS; k += 32) {
                float v = xr[k];
                *(float2*)&sa[k * PITCHD + 2 * b] = make_float2(v, v);
            }
            if (lane < 2) {
                float v = g_y[row * 2 + lane];
                *(float2*)&sa[(OBS + lane) * PITCHD + 2 * b] = make_float2(v, v);
            }
            const float* hr = &g_hbuf[0][(size_t)row * HID];
            for (int k = lane; k < HID; k += 32) {
                float v = hr[k];
                *(float2*)&sa[(INP + k) * PITCHD + 2 * b] = make_float2(v, v);
            }
        }
        __syncthreads();
    }

    for (int t = 0; t < SEQ; t++) {
        // ---------- gates GEMM: 4 batch x 4 cols per thread, zero-MOV ----------
        ull acc[4][2];
#pragma unroll
        for (int b = 0; b < 4; b++) {
            acc[b][0] = pack2(bA.x, bA.y);     // (i,f)
            acc[b][1] = pack2(bA.z, bA.w);     // (g,o)
        }
        const float* wp = g_Wt + colbase;
        const float* ap = sa + ty * 8;         // pairs: (a0,a0,a1,a1) / (a2,a2,a3,a3)

        ulonglong2 wbuf[4];
#pragma unroll
        for (int r = 0; r < 4; r++) wbuf[r] = *(const ulonglong2*)(wp + (size_t)r * GAT);

#pragma unroll 8
        for (int k = 0; k < KTOT; k++) {
            ulonglong2 w   = wbuf[k & 3];
            ulonglong2 A01 = *(const ulonglong2*)(ap + k * PITCHD);       // dup a0,a1
            ulonglong2 A23 = *(const ulonglong2*)(ap + k * PITCHD + 4);   // dup a2,a3
            int kp = k + 4;
            if (kp < KTOT) wbuf[k & 3] = *(const ulonglong2*)(wp + (size_t)kp * GAT);
            fma2(acc[0][0], A01.x, w.x); fma2(acc[0][1], A01.x, w.y);
            fma2(acc[1][0], A01.y, w.x); fma2(acc[1][1], A01.y, w.y);
            fma2(acc[2][0], A23.x, w.x); fma2(acc[2][1], A23.x, w.y);
            fma2(acc[3][0], A23.y, w.x); fma2(acc[3][1], A23.y, w.y);
        }

        // ---------- cell update (registers) + h write ----------
        const int wb = (t + 1) & 1;
#pragma unroll
        for (int b = 0; b < 4; b++) {
            float2 p0 = unpack2(acc[b][0]);   // (i,f)
            float2 p1 = unpack2(acc[b][1]);   // (g,o)
            float nc = sigm(p0.y) * c[b] + sigm(p0.x) * tanh_(p1.x);
            float h  = sigm(p1.y) * tanh_(nc);
            c[b] = nc;
            int row = rowbase + b;
            __stcg(&g_hbuf[wb][(size_t)row * HID + u], h);
            if (t == SEQ - 1) {
                out[OFF_H + (size_t)row * HID + u] = h;
                out[OFF_C + (size_t)row * HID + u] = nc;
            }
        }

        cluster_sync_();   // h_t visible to the 7 peer CTAs (same bt)

        // ---------- overlapped: stage next step (x,h) + MLP(h_t) ----------
        const float* hb = g_hbuf[wb];

        if (t < SEQ - 1) {     // stage x_{t+1}, h_t (y patched after 2nd sync)
            int tn = t + 1;
#pragma unroll
            for (int i = 0; i < 2; i++) {
                int b = wid * 2 + i;
                int row = bt * 32 + b;
                const float* xr = x + (size_t)row * SEQ * OBS + (size_t)tn * OBS;
                for (int k = lane; k < OBS; k += 32) {
                    float v = xr[k];
                    *(float2*)&sa[k * PITCHD + 2 * b] = make_float2(v, v);
                }
                const float* hr = &hb[(size_t)row * HID];
                for (int k = lane; k < HID; k += 32) {
                    float v = __ldcg(&hr[k]);
                    *(float2*)&sa[(INP + k) * PITCHD + 2 * b] = make_float2(v, v);
                }
            }
        }

        // copy 4 MLP rows of h into smem, transposed [k][r]
        for (int i = tid; i < 4 * HID; i += NTHR) {
            int r = i >> 9, k = i & (HID - 1);
            hbufS[k * 4 + r] = __ldcg(&hb[(size_t)(mrowb + r) * HID + k]);
        }
        __syncthreads();

        {   // layer 1: all 512 threads, 8-way k-split; thread=(ks,u1), 4 rows each
            int ks = tid >> 6, u1 = tid & 63;
            const float* wq = g_W1t + (size_t)(ks * 64) * 64 + u1;
            const float* hq = hbufS + ks * 64 * 4;
            float a0 = 0.f, a1 = 0.f, a2 = 0.f, a3 = 0.f;
#pragma unroll 4
            for (int kk = 0; kk < 64; kk++) {
                float w = __ldg(wq + (size_t)kk * 64);
                float4 hv = *(const float4*)(hq + kk * 4);   // broadcast LDS.128
                a0 = fmaf(hv.x, w, a0);
                a1 = fmaf(hv.y, w, a1);
                a2 = fmaf(hv.z, w, a2);
                a3 = fmaf(hv.w, w, a3);
            }
            float* pp = p1s + ks * 256 + u1;
            pp[0]   = a0;
            pp[64]  = a1;
            pp[128] = a2;
            pp[192] = a3;
        }
        __syncthreads();
        if (tid < 256) {  // layer 1 combine + relu
            int r = tid >> 6, u1 = tid & 63;
            float v = __ldg(&b1[u1]);
#pragma unroll
            for (int ks = 0; ks < 8; ks++) v += p1s[ks * 256 + r * 64 + u1];
            y1s[r * 64 + u1] = fmaxf(v, 0.f);
        }
        __syncthreads();
        if (tid < 64) {   // layer 2: 64 -> 16
            int r = tid >> 4, u2 = tid & 15;
            const float* yr = y1s + r * 64;
            float v = __ldg(&b2[u2]);
#pragma unroll
            for (int kk = 0; kk < 64; kk++)
                v = fmaf(yr[kk], __ldg(&g_W2t[kk * 16 + u2]), v);
            y2s[r * 16 + u2] = fmaxf(v, 0.f);
        }
        __syncthreads();
        if (tid < 8) {    // layer 3: 16 -> 2, write y + output
            int r = tid >> 1, j = tid & 1;
            const float* yr = y2s + r * 16;
            float v = __ldg(&b3[j]);
#pragma unroll
            for (int kk = 0; kk < 16; kk++) v = fmaf(yr[kk], __ldg(&W3[j * 16 + kk]), v);
            v = fmaxf(v, 0.f);
            int row = mrowb + r;
            __stcg(&g_y[row * 2 + j], v);
            out[(size_t)row * SEQ * 2 + (size_t)t * 2 + j] = v;
        }

        if (t < SEQ - 1) {
            cluster_sync_();       // y_t visible within cluster
            if (tid < 64) {        // patch fed-back pos (duplicated) into staged input
                int b = tid >> 1, j = tid & 1;
                int row = bt * 32 + b;
                float v = __ldcg(&g_y[row * 2 + j]);
                *(float2*)&sa[(OBS + j) * PITCHD + 2 * b] = make_float2(v, v);
            }
            __syncthreads();
        }
    }
}

extern "C" void kernel_launch(void* const* d_in, const int* in_sizes, int n_in,
                              void* d_out, int out_size) {
    const float* x      = (const float*)d_in[0];
    const float* pos    = (const float*)d_in[1];
    const float* hidden = (const float*)d_in[2];
    const float* cell   = (const float*)d_in[3];
    const float* W_ih   = (const float*)d_in[4];
    const float* W_hh   = (const float*)d_in[5];
    const float* b_ih   = (const float*)d_in[6];
    const float* b_hh   = (const float*)d_in[7];
    const float* W1     = (const float*)d_in[8];
    const float* b1     = (const float*)d_in[9];
    const float* W2     = (const float*)d_in[10];
    const float* b2     = (const float*)d_in[11];
    const float* W3     = (const float*)d_in[12];
    const float* b3     = (const float*)d_in[13];
    float* out = (float*)d_out;

    cudaFuncSetAttribute((const void*)lstm_persistent,
                         cudaFuncAttributeMaxDynamicSharedMemorySize, SMEM_BYTES);

    precompute_kernel<<<512, 256>>>(W_ih, W_hh, b_ih, b_hh, hidden, pos, W1, W2);
    lstm_persistent<<<NBLK, NTHR, SMEM_BYTES>>>(x, cell, b1, b2, W3, b3, out);
}

// round 14
// speedup vs baseline: 2.0207x; 2.0207x over previous
#include <cuda_runtime.h>
#include <cstdint>

#define BATCH 512
#define SEQ   512
#define OBS   103
#define HID   512
#define INP   105            // OBS + 2 fed-back pos
#define KEFF  615            // OBS + HID (pos handled separately)
#define GAT   2048           // 4*HID
#define NBLK  128
#define NTHR  512
#define PITCHD 68            // dup'd smem k-row pitch (64 dup floats + pad, 16B-aligned)
#define OFF_H (BATCH*SEQ*2)
#define OFF_C (OFF_H + BATCH*HID)
#define SA_FLOATS (KEFF*PITCHD)       // 41820
#define SMEM_FLOATS (SA_FLOATS + 2048 + 2048 + 256 + 64)
#define SMEM_BYTES  (SMEM_FLOATS*4)   // ~185 KB

typedef unsigned long long ull;

// ---- static device scratch (no allocation allowed) ----
__device__ __align__(16) float g_Wt[KEFF*GAT];   // k-major (x,h rows), gate-interleaved cols
__device__ __align__(16) float g_Wpos[2*GAT];    // pos rows (k=103,104), same col layout
__device__ __align__(16) float g_bias[GAT];      // b_ih+b_hh, permuted
__device__ __align__(16) float g_W1t[HID*64];    // layer1 weights, k-major
__device__ __align__(16) float g_W2t[64*16];     // layer2 weights, k-major
__device__ __align__(16) float g_hbuf[2][BATCH*HID];
__device__ __align__(16) float g_y[BATCH*2];
__device__ unsigned g_hcnt[16];   // per-bt h release counters (monotonic)
__device__ unsigned g_ycnt[16];   // per-bt y release counters (monotonic)

// ---- packed f32x2 helpers ----
__device__ __forceinline__ ull dup2(float x) {
    ull r; asm("mov.b64 %0, {%1, %1};" : "=l"(r) : "f"(x)); return r;
}
__device__ __forceinline__ ull pack2(float lo, float hi) {
    ull r; asm("mov.b64 %0, {%1, %2};" : "=l"(r) : "f"(lo), "f"(hi)); return r;
}
__device__ __forceinline__ float2 unpack2(ull v) {
    float lo, hi; asm("mov.b64 {%0, %1}, %2;" : "=f"(lo), "=f"(hi) : "l"(v));
    return make_float2(lo, hi);
}
__device__ __forceinline__ void fma2(ull &d, ull a, ull b) {
    asm("fma.rn.f32x2 %0, %1, %2, %0;" : "+l"(d) : "l"(a), "l"(b));
}

__device__ __forceinline__ float sigm(float x) { return 1.f / (1.f + __expf(-x)); }
__device__ __forceinline__ float tanh_(float x) {
    x = fminf(15.f, fmaxf(-15.f, x));
    float e = __expf(-2.f * x);
    return (1.f - e) / (1.f + e);
}

// ---- precompute: permuted transpose of W, combined bias, state init ----
__global__ void precompute_kernel(const float* __restrict__ W_ih,
                                  const float* __restrict__ W_hh,
                                  const float* __restrict__ b_ih,
                                  const float* __restrict__ b_hh,
                                  const float* __restrict__ hidden,
                                  const float* __restrict__ pos,
                                  const float* __restrict__ W1,
                                  const float* __restrict__ W2) {
    const int stride = gridDim.x * blockDim.x;
    const int i0 = blockIdx.x * blockDim.x + threadIdx.x;
    // Wt[k][col]; col = ubp*256 + ul*4 + g  <->  original row r = g*HID + ubp*64 + ul
    // k < 103 -> x part (W_ih col k); k >= 103 -> h part (W_hh col k-103)
    for (int idx = i0; idx < KEFF * GAT; idx += stride) {
        int k = idx >> 11, col = idx & 2047;
        int ubp = col >> 8, rem = col & 255, ul = rem >> 2, g = rem & 3;
        int r = g * HID + ubp * 64 + ul;
        g_Wt[idx] = (k < OBS) ? W_ih[r * INP + k] : W_hh[r * HID + (k - OBS)];
    }
    for (int idx = i0; idx < 2 * GAT; idx += stride) {
        int j = idx >> 11, col = idx & 2047;
        int ubp = col >> 8, rem = col & 255, ul = rem >> 2, g = rem & 3;
        int r = g * HID + ubp * 64 + ul;
        g_Wpos[idx] = W_ih[r * INP + OBS + j];
    }
    for (int col = i0; col < GAT; col += stride) {
        int ubp = col >> 8, rem = col & 255, ul = rem >> 2, g = rem & 3;
        int r = g * HID + ubp * 64 + ul;
        g_bias[col] = b_ih[r] + b_hh[r];
    }
    for (int idx = i0; idx < HID * 64; idx += stride) {
        int k = idx >> 6, u1 = idx & 63;
        g_W1t[idx] = W1[u1 * HID + k];
    }
    for (int idx = i0; idx < 64 * 16; idx += stride) {
        int k = idx >> 4, u2 = idx & 15;
        g_W2t[idx] = W2[u2 * 64 + k];
    }
    for (int idx = i0; idx < BATCH * HID; idx += stride) g_hbuf[0][idx] = hidden[idx];
    if (i0 < 16) { g_hcnt[i0] = 0; g_ycnt[i0] = 0; }
}

// ---- persistent LSTM kernel ----
__global__ void __launch_bounds__(NTHR, 1)
lstm_persistent(const float* __restrict__ x,
                const float* __restrict__ pos,
                const float* __restrict__ cell,
                const float* __restrict__ b1,
                const float* __restrict__ b2,
                const float* __restrict__ W3, const float* __restrict__ b3,
                float* __restrict__ out) {
    extern __shared__ float sm[];
    float* sa    = sm;                     // staged (x,h) DUPLICATED, [KEFF][PITCHD]
    float* hbufS = sm + SA_FLOATS;         // MLP h, transposed [512 k][4 rows]
    float* p1s   = hbufS + 2048;           // layer1 partials [8 ks][4 r][64 u1]
    float* y1s   = p1s + 2048;             // 4*64
    float* y2s   = y1s + 256;              // 4*16

    const int tid  = threadIdx.x;
    const int lane = tid & 31;
    const int wid  = tid >> 5;             // 0..15
    const int bt = blockIdx.x >> 3, ct = blockIdx.x & 7;
    const int tx = tid & 63, ty = tid >> 6;   // tx: unit, ty: batch group
    const int colbase = ct * 256 + tx * 4;    // one unit = 4 interleaved gates
    const int rowbase = bt * 32 + ty * 4;
    const int u       = ct * 64 + tx;         // global hidden unit
    const int mrowb   = blockIdx.x * 4;       // MLP rows for this block

    const float4 bA = *(const float4*)(g_bias + colbase);
    // pos-column weights, register-resident for the whole kernel
    const ulonglong2 wp0 = *(const ulonglong2*)(g_Wpos + colbase);
    const ulonglong2 wp1 = *(const ulonglong2*)(g_Wpos + GAT + colbase);

    // cell state in registers: 4 batch rows x 1 unit
    float c[4];
#pragma unroll
    for (int b = 0; b < 4; b++) c[b] = cell[(size_t)(rowbase + b) * HID + u];

    // ---------- prologue: stage step-0 (x0, h0) duplicated ----------
    {
#pragma unroll
        for (int i = 0; i < 2; i++) {
            int b = wid * 2 + i;
            int row = bt * 32 + b;
            const float* xr = x + (size_t)row * SEQ * OBS;
            for (int k = lane; k < OBS; k += 32) {
                float v = xr[k];
                *(float2*)&sa[k * PITCHD + 2 * b] = make_float2(v, v);
            }
            const float* hr = &g_hbuf[0][(size_t)row * HID];
            for (int k = lane; k < HID; k += 32) {
                float v = hr[k];
                *(float2*)&sa[(OBS + k) * PITCHD + 2 * b] = make_float2(v, v);
            }
        }
        __syncthreads();
    }

    for (int t = 0; t < SEQ; t++) {
        // ---------- gates GEMM over x,h (615 cols): zero-MOV f32x2 ----------
        ull acc[4][2];
#pragma unroll
        for (int b = 0; b < 4; b++) {
            acc[b][0] = pack2(bA.x, bA.y);     // (i,f)
            acc[b][1] = pack2(bA.z, bA.w);     // (g,o)
        }
        const float* wp = g_Wt + colbase;
        const float* ap = sa + ty * 8;         // pairs: (a0,a0,a1,a1) / (a2,a2,a3,a3)

        ulonglong2 wbuf[4];
#pragma unroll
        for (int r = 0; r < 4; r++) wbuf[r] = *(const ulonglong2*)(wp + (size_t)r * GAT);

#pragma unroll 8
        for (int k = 0; k < KEFF; k++) {
            ulonglong2 w   = wbuf[k & 3];
            ulonglong2 A01 = *(const ulonglong2*)(ap + k * PITCHD);       // dup a0,a1
            ulonglong2 A23 = *(const ulonglong2*)(ap + k * PITCHD + 4);   // dup a2,a3
            int kp = k + 4;
            if (kp < KEFF) wbuf[k & 3] = *(const ulonglong2*)(wp + (size_t)kp * GAT);
            fma2(acc[0][0], A01.x, w.x); fma2(acc[0][1], A01.x, w.y);
            fma2(acc[1][0], A01.y, w.x); fma2(acc[1][1], A01.y, w.y);
            fma2(acc[2][0], A23.x, w.x); fma2(acc[2][1], A23.x, w.y);
            fma2(acc[3][0], A23.y, w.x); fma2(acc[3][1], A23.y, w.y);
        }

        // ---------- deferred pos contribution (y_{t-1}) ----------
        if (t > 0) {
            if (tid == 0) {
                while (*(volatile unsigned*)&g_ycnt[bt] < 64u * (unsigned)t) { }
            }
            __syncthreads();
        }
#pragma unroll
        for (int b = 0; b < 4; b++) {
            int row = rowbase + b;
            float y0v, y1v;
            if (t == 0) {
                y0v = pos[(size_t)row * SEQ * 2];
                y1v = pos[(size_t)row * SEQ * 2 + 1];
            } else {
                y0v = __ldcg(&g_y[row * 2]);
                y1v = __ldcg(&g_y[row * 2 + 1]);
            }
            ull Y0 = dup2(y0v), Y1 = dup2(y1v);
            fma2(acc[b][0], Y0, wp0.x); fma2(acc[b][1], Y0, wp0.y);
            fma2(acc[b][0], Y1, wp1.x); fma2(acc[b][1], Y1, wp1.y);
        }

        // ---------- cell update (registers) + h write ----------
        const int wb = (t + 1) & 1;
#pragma unroll
        for (int b = 0; b < 4; b++) {
            float2 p0 = unpack2(acc[b][0]);   // (i,f)
            float2 p1 = unpack2(acc[b][1]);   // (g,o)
            float nc = sigm(p0.y) * c[b] + sigm(p0.x) * tanh_(p1.x);
            float h  = sigm(p1.y) * tanh_(nc);
            c[b] = nc;
            int row = rowbase + b;
            __stcg(&g_hbuf[wb][(size_t)row * HID + u], h);
            if (t == SEQ - 1) {
                out[OFF_H + (size_t)row * HID + u] = h;
                out[OFF_C + (size_t)row * HID + u] = nc;
            }
        }

        // ---------- per-bt h barrier (8 blocks, monotonic counter) ----------
        __threadfence();
        __syncthreads();
        if (tid == 0) {
            atomicAdd(&g_hcnt[bt], 1u);
            while (*(volatile unsigned*)&g_hcnt[bt] < 8u * (unsigned)(t + 1)) { }
        }
        __syncthreads();

        // ---------- overlapped: stage next step (x,h) + MLP(h_t) ----------
        const float* hb = g_hbuf[wb];

        if (t < SEQ - 1) {     // stage x_{t+1}, h_t
            int tn = t + 1;
#pragma unroll
            for (int i = 0; i < 2; i++) {
                int b = wid * 2 + i;
                int row = bt * 32 + b;
                const float* xr = x + (size_t)row * SEQ * OBS + (size_t)tn * OBS;
                for (int k = lane; k < OBS; k += 32) {
                    float v = xr[k];
                    *(float2*)&sa[k * PITCHD + 2 * b] = make_float2(v, v);
                }
                const float* hr = &hb[(size_t)row * HID];
                for (int k = lane; k < HID; k += 32) {
                    float v = __ldcg(&hr[k]);
                    *(float2*)&sa[(OBS + k) * PITCHD + 2 * b] = make_float2(v, v);
                }
            }
        }

        // copy 4 MLP rows of h into smem, transposed [k][r]
        for (int i = tid; i < 4 * HID; i += NTHR) {
            int r = i >> 9, k = i & (HID - 1);
            hbufS[k * 4 + r] = __ldcg(&hb[(size_t)(mrowb + r) * HID + k]);
        }
        __syncthreads();

        {   // layer 1: all 512 threads, 8-way k-split; thread=(ks,u1), 4 rows each
            int ks = tid >> 6, u1 = tid & 63;
            const float* wq = g_W1t + (size_t)(ks * 64) * 64 + u1;
            const float* hq = hbufS + ks * 64 * 4;
            float a0 = 0.f, a1 = 0.f, a2 = 0.f, a3 = 0.f;
#pragma unroll 4
            for (int kk = 0; kk < 64; kk++) {
                float w = __ldg(wq + (size_t)kk * 64);
                float4 hv = *(const float4*)(hq + kk * 4);   // broadcast LDS.128
                a0 = fmaf(hv.x, w, a0);
                a1 = fmaf(hv.y, w, a1);
                a2 = fmaf(hv.z, w, a2);
                a3 = fmaf(hv.w, w, a3);
            }
            float* pp = p1s + ks * 256 + u1;
            pp[0]   = a0;
            pp[64]  = a1;
            pp[128] = a2;
            pp[192] = a3;
        }
        __syncthreads();
        if (tid < 256) {  // layer 1 combine + relu
            int r = tid >> 6, u1 = tid & 63;
            float v = __ldg(&b1[u1]);
#pragma unroll
            for (int ks = 0; ks < 8; ks++) v += p1s[ks * 256 + r * 64 + u1];
            y1s[r * 64 + u1] = fmaxf(v, 0.f);
        }
        __syncthreads();
        if (tid < 64) {   // layer 2: 64 -> 16
            int r = tid >> 4, u2 = tid & 15;
            const float* yr = y1s + r * 64;
            float v = __ldg(&b2[u2]);
#pragma unroll
            for (int kk = 0; kk < 64; kk++)
                v = fmaf(yr[kk], __ldg(&g_W2t[kk * 16 + u2]), v);
            y2s[r * 16 + u2] = fmaxf(v, 0.f);
        }
        __syncthreads();
        if (tid < 8) {    // layer 3: 16 -> 2, write y + release
            int r = tid >> 1, j = tid & 1;
            const float* yr = y2s + r * 16;
            float v = __ldg(&b3[j]);
#pragma unroll
            for (int kk = 0; kk < 16; kk++) v = fmaf(yr[kk], __ldg(&W3[j * 16 + kk]), v);
            v = fmaxf(v, 0.f);
            int row = mrowb + r;
            __stcg(&g_y[row * 2 + j], v);
            out[(size_t)row * SEQ * 2 + (size_t)t * 2 + j] = v;
            __threadfence();                 // release y write
            atomicAdd(&g_ycnt[bt], 1u);      // 8 per block -> 64 per bt per step
        }

        __syncthreads();   // staging + MLP complete before next GEMM reads sa
    }
}

extern "C" void kernel_launch(void* const* d_in, const int* in_sizes, int n_in,
                              void* d_out, int out_size) {
    const float* x      = (const float*)d_in[0];
    const float* pos    = (const float*)d_in[1];
    const float* hidden = (const float*)d_in[2];
    const float* cell   = (const float*)d_in[3];
    const float* W_ih   = (const float*)d_in[4];
    const float* W_hh   = (const float*)d_in[5];
    const float* b_ih   = (const float*)d_in[6];
    const float* b_hh   = (const float*)d_in[7];
    const float* W1     = (const float*)d_in[8];
    const float* b1     = (const float*)d_in[9];
    const float* W2     = (const float*)d_in[10];
    const float* b2     = (const float*)d_in[11];
    const float* W3     = (const float*)d_in[12];
    const float* b3     = (const float*)d_in[13];
    float* out = (float*)d_out;

    cudaFuncSetAttribute((const void*)lstm_persistent,
                         cudaFuncAttributeMaxDynamicSharedMemorySize, SMEM_BYTES);

    precompute_kernel<<<512, 256>>>(W_ih, W_hh, b_ih, b_hh, hidden, pos, W1, W2);
    lstm_persistent<<<NBLK, NTHR, SMEM_BYTES>>>(x, pos, cell, b1, b2, W3, b3, out);
}

// round 16
// speedup vs baseline: 2.1758x; 1.0767x over previous
#include <cuda_runtime.h>
#include <cstdint>

#define BATCH 512
#define SEQ   512
#define OBS   103
#define HID   512
#define INP   105            // OBS + 2 fed-back pos
#define KEFF  615            // OBS + HID (pos handled separately)
#define KP    616            // padded (row 615 = zeros) so 2 k-halves of 308
#define KHALF 308
#define GAT   2048           // 4*HID
#define NBLK  128
#define NTHR  512
#define PITCHD 68            // dup'd smem k-row pitch (64 dup floats + pad)
#define OFF_H (BATCH*SEQ*2)
#define OFF_C (OFF_H + BATCH*HID)
#define SA_FLOATS  (KP*PITCHD)        // 41888
#define RED_FLOATS 8192               // 16 ull x 256 threads = 32KB
#define SMEM_FLOATS (SA_FLOATS + RED_FLOATS + 2048 + 2048 + 256 + 64)
#define SMEM_BYTES  (SMEM_FLOATS*4)   // 217,984 B

typedef unsigned long long ull;

// ---- static device scratch (no allocation allowed) ----
__device__ __align__(16) float g_Wt[KP*GAT];     // k-major (x,h rows + zero row), gate-interleaved
__device__ __align__(16) float g_Wpos[2*GAT];    // pos rows, same col layout
__device__ __align__(16) float g_bias[GAT];      // b_ih+b_hh, permuted
__device__ __align__(16) float g_W1t[HID*64];    // layer1 weights, k-major
__device__ __align__(16) float g_W2t[64*16];     // layer2 weights, k-major
__device__ __align__(16) float g_hbuf[2][BATCH*HID];
__device__ __align__(16) float g_y[BATCH*2];
__device__ unsigned g_hcnt[16];   // per-bt h release counters (monotonic)
__device__ unsigned g_ycnt[16];   // per-bt y release counters (monotonic)

// ---- packed f32x2 helpers ----
__device__ __forceinline__ ull dup2(float x) {
    ull r; asm("mov.b64 %0, {%1, %1};" : "=l"(r) : "f"(x)); return r;
}
__device__ __forceinline__ ull pack2(float lo, float hi) {
    ull r; asm("mov.b64 %0, {%1, %2};" : "=l"(r) : "f"(lo), "f"(hi)); return r;
}
__device__ __forceinline__ float2 unpack2(ull v) {
    float lo, hi; asm("mov.b64 {%0, %1}, %2;" : "=f"(lo), "=f"(hi) : "l"(v));
    return make_float2(lo, hi);
}
__device__ __forceinline__ void fma2(ull &d, ull a, ull b) {
    asm("fma.rn.f32x2 %0, %1, %2, %0;" : "+l"(d) : "l"(a), "l"(b));
}
__device__ __forceinline__ ull addf2(ull a, ull b) {
    ull r; asm("add.rn.f32x2 %0, %1, %2;" : "=l"(r) : "l"(a), "l"(b)); return r;
}

__device__ __forceinline__ float sigm(float x) { return 1.f / (1.f + __expf(-x)); }
__device__ __forceinline__ float tanh_(float x) {
    x = fminf(15.f, fmaxf(-15.f, x));
    float e = __expf(-2.f * x);
    return (1.f - e) / (1.f + e);
}

// ---- precompute: permuted transpose of W, combined bias, state init ----
__global__ void precompute_kernel(const float* __restrict__ W_ih,
                                  const float* __restrict__ W_hh,
                                  const float* __restrict__ b_ih,
                                  const float* __restrict__ b_hh,
                                  const float* __restrict__ hidden,
                                  const float* __restrict__ pos,
                                  const float* __restrict__ W1,
                                  const float* __restrict__ W2) {
    const int stride = gridDim.x * blockDim.x;
    const int i0 = blockIdx.x * blockDim.x + threadIdx.x;
    // Wt[k][col]; col = ubp*256 + ul*4 + g  <->  original row r = g*HID + ubp*64 + ul
    for (size_t idx = i0; idx < (size_t)KP * GAT; idx += stride) {
        int k = (int)(idx >> 11), col = (int)(idx & 2047);
        int ubp = col >> 8, rem = col & 255, ul = rem >> 2, g = rem & 3;
        int r = g * HID + ubp * 64 + ul;
        float v;
        if (k < OBS)       v = W_ih[r * INP + k];
        else if (k < KEFF) v = W_hh[r * HID + (k - OBS)];
        else               v = 0.f;   // padded row
        g_Wt[idx] = v;
    }
    for (int idx = i0; idx < 2 * GAT; idx += stride) {
        int j = idx >> 11, col = idx & 2047;
        int ubp = col >> 8, rem = col & 255, ul = rem >> 2, g = rem & 3;
        int r = g * HID + ubp * 64 + ul;
        g_Wpos[idx] = W_ih[r * INP + OBS + j];
    }
    for (int col = i0; col < GAT; col += stride) {
        int ubp = col >> 8, rem = col & 255, ul = rem >> 2, g = rem & 3;
        int r = g * HID + ubp * 64 + ul;
        g_bias[col] = b_ih[r] + b_hh[r];
    }
    for (int idx = i0; idx < HID * 64; idx += stride) {
        int k = idx >> 6, u1 = idx & 63;
        g_W1t[idx] = W1[u1 * HID + k];
    }
    for (int idx = i0; idx < 64 * 16; idx += stride) {
        int k = idx >> 4, u2 = idx & 15;
        g_W2t[idx] = W2[u2 * 64 + k];
    }
    for (int idx = i0; idx < BATCH * HID; idx += stride) g_hbuf[0][idx] = hidden[idx];
    if (i0 < 16) { g_hcnt[i0] = 0; g_ycnt[i0] = 0; }
}

// ---- persistent LSTM kernel ----
__global__ void __launch_bounds__(NTHR, 1)
lstm_persistent(const float* __restrict__ x,
                const float* __restrict__ pos,
                const float* __restrict__ cell,
                const float* __restrict__ b1,
                const float* __restrict__ b2,
                const float* __restrict__ W3, const float* __restrict__ b3,
                float* __restrict__ out) {
    extern __shared__ float sm[];
    float* sa    = sm;                     // staged (x,h) DUPLICATED, [KP][PITCHD]
    ull*   red   = (ull*)(sm + SA_FLOATS); // split-k partials [16 ull][256 thr]
    float* hbufS = sm + SA_FLOATS + RED_FLOATS;   // MLP h, transposed [512 k][4 rows]
    float* p1s   = hbufS + 2048;           // layer1 partials [8 ks][4 r][64 u1]
    float* y1s   = p1s + 2048;             // 4*64
    float* y2s   = y1s + 256;              // 4*16

    const int tid  = threadIdx.x;
    const int lane = tid & 31;
    const int wid  = tid >> 5;             // 0..15
    const int bt = blockIdx.x >> 3, ct = blockIdx.x & 7;
    const int tx = tid & 63, ty = tid >> 6;   // tx: unit
    const int rg = ty & 3, kh = ty >> 2;      // rg: 8-row group, kh: k-half
    const int colbase = ct * 256 + tx * 4;    // one unit = 4 interleaved gates
    const int rowb8   = bt * 32 + rg * 8;     // this thread's 8 rows
    const int u       = ct * 64 + tx;         // global hidden unit
    const int mrowb   = blockIdx.x * 4;       // MLP rows for this block
    const int jred    = rg * 64 + tx;         // reduction slot (0..255)

    const float4 bA = *(const float4*)(g_bias + colbase);
    const ulonglong2 wp0 = *(const ulonglong2*)(g_Wpos + colbase);
    const ulonglong2 wp1 = *(const ulonglong2*)(g_Wpos + GAT + colbase);

    // cell state in registers (kh==0 threads own the cell update): 8 rows x 1 unit
    float c[8];
    if (kh == 0) {
#pragma unroll
        for (int b = 0; b < 8; b++) c[b] = cell[(size_t)(rowb8 + b) * HID + u];
    }

    // ---------- prologue: stage step-0 (x0, h0) duplicated; zero pad row ----------
    {
#pragma unroll
        for (int i = 0; i < 2; i++) {
            int b = wid * 2 + i;
            int row = bt * 32 + b;
            const float* xr = x + (size_t)row * SEQ * OBS;
            for (int k = lane; k < OBS; k += 32) {
                float v = xr[k];
                *(float2*)&sa[k * PITCHD + 2 * b] = make_float2(v, v);
            }
            const float* hr = &g_hbuf[0][(size_t)row * HID];
            for (int k = lane; k < HID; k += 32) {
                float v = hr[k];
                *(float2*)&sa[(OBS + k) * PITCHD + 2 * b] = make_float2(v, v);
            }
        }
        if (tid < 64) sa[KEFF * PITCHD + tid] = 0.f;   // padded k row = 0
        __syncthreads();
    }

    for (int t = 0; t < SEQ; t++) {
        // ---------- gates GEMM, split-k: 8 rows x 4 gates x half-k per thread ----------
        ull acc[8][2];
        if (kh == 0) {
#pragma unroll
            for (int b = 0; b < 8; b++) {
                acc[b][0] = pack2(bA.x, bA.y);     // (i,f)
                acc[b][1] = pack2(bA.z, bA.w);     // (g,o)
            }
        } else {
#pragma unroll
            for (int b = 0; b < 8; b++) { acc[b][0] = 0ull; acc[b][1] = 0ull; }
        }
        const float* wp = g_Wt + colbase;
        const float* ap = sa + rg * 16;        // 8 dup'd rows = 16 floats
        const int k0 = kh * KHALF, kend = k0 + KHALF;

        ulonglong2 wbuf[4];
#pragma unroll
        for (int r = 0; r < 4; r++)
            wbuf[r] = *(const ulonglong2*)(wp + (size_t)(k0 + r) * GAT);

#pragma unroll 4
        for (int k = k0; k < kend; k++) {
            ulonglong2 w = wbuf[k & 3];
            const float* a = ap + (size_t)k * PITCHD;
            ulonglong2 A01 = *(const ulonglong2*)(a);
            ulonglong2 A23 = *(const ulonglong2*)(a + 4);
            ulonglong2 A45 = *(const ulonglong2*)(a + 8);
            ulonglong2 A67 = *(const ulonglong2*)(a + 12);
            int kp = k + 4;
            if (kp < kend) wbuf[k & 3] = *(const ulonglong2*)(wp + (size_t)kp * GAT);
            fma2(acc[0][0], A01.x, w.x); fma2(acc[0][1], A01.x, w.y);
            fma2(acc[1][0], A01.y, w.x); fma2(acc[1][1], A01.y, w.y);
            fma2(acc[2][0], A23.x, w.x); fma2(acc[2][1], A23.x, w.y);
            fma2(acc[3][0], A23.y, w.x); fma2(acc[3][1], A23.y, w.y);
            fma2(acc[4][0], A45.x, w.x); fma2(acc[4][1], A45.x, w.y);
            fma2(acc[5][0], A45.y, w.x); fma2(acc[5][1], A45.y, w.y);
            fma2(acc[6][0], A67.x, w.x); fma2(acc[6][1], A67.x, w.y);
            fma2(acc[7][0], A67.y, w.x); fma2(acc[7][1], A67.y, w.y);
        }

        // ---------- split-k reduction via smem ----------
        if (kh == 1) {
#pragma unroll
            for (int b = 0; b < 8; b++) {
                red[(2 * b) * 256 + jred]     = acc[b][0];
                red[(2 * b + 1) * 256 + jred] = acc[b][1];
            }
        }
        __syncthreads();

        // ---------- wait for y_{t-1} (produced ~a full GEMM ago; near-free) ----------
        if (t > 0) {
            if (tid == 0) {
                while (*(volatile unsigned*)&g_ycnt[bt] < 64u * (unsigned)t) { }
            }
            __syncthreads();
        }

        const int wb = (t + 1) & 1;
        if (kh == 0) {
            // combine halves + deferred pos + cell update + h write (8 rows)
#pragma unroll
            for (int b = 0; b < 8; b++) {
                acc[b][0] = addf2(acc[b][0], red[(2 * b) * 256 + jred]);
                acc[b][1] = addf2(acc[b][1], red[(2 * b + 1) * 256 + jred]);
                int row = rowb8 + b;
                float y0v, y1v;
                if (t == 0) {
                    y0v = pos[(size_t)row * SEQ * 2];
                    y1v = pos[(size_t)row * SEQ * 2 + 1];
                } else {
                    y0v = __ldcg(&g_y[row * 2]);
                    y1v = __ldcg(&g_y[row * 2 + 1]);
                }
                ull Y0 = dup2(y0v), Y1 = dup2(y1v);
                fma2(acc[b][0], Y0, wp0.x); fma2(acc[b][1], Y0, wp0.y);
                fma2(acc[b][0], Y1, wp1.x); fma2(acc[b][1], Y1, wp1.y);
                float2 p0 = unpack2(acc[b][0]);   // (i,f)
                float2 p1 = unpack2(acc[b][1]);   // (g,o)
                float nc = sigm(p0.y) * c[b] + sigm(p0.x) * tanh_(p1.x);
                float h  = sigm(p1.y) * tanh_(nc);
                c[b] = nc;
                __stcg(&g_hbuf[wb][(size_t)row * HID + u], h);
                if (t == SEQ - 1) {
                    out[OFF_H + (size_t)row * HID + u] = h;
                    out[OFF_C + (size_t)row * HID + u] = nc;
                }
            }
        }

        // ---------- per-bt h barrier (8 blocks, monotonic counter) ----------
        __threadfence();
        __syncthreads();
        if (tid == 0) {
            atomicAdd(&g_hcnt[bt], 1u);
            while (*(volatile unsigned*)&g_hcnt[bt] < 8u * (unsigned)(t + 1)) { }
        }
        __syncthreads();

        // ---------- overlapped: stage next step (x,h) + MLP(h_t) ----------
        const float* hb = g_hbuf[wb];

        if (t < SEQ - 1) {     // stage x_{t+1}, h_t
            int tn = t + 1;
#pragma unroll
            for (int i = 0; i < 2; i++) {
                int b = wid * 2 + i;
                int row = bt * 32 + b;
                const float* xr = x + (size_t)row * SEQ * OBS + (size_t)tn * OBS;
                for (int k = lane; k < OBS; k += 32) {
                    float v = xr[k];
                    *(float2*)&sa[k * PITCHD + 2 * b] = make_float2(v, v);
                }
                const float* hr = &hb[(size_t)row * HID];
                for (int k = lane; k < HID; k += 32) {
                    float v = __ldcg(&hr[k]);
                    *(float2*)&sa[(OBS + k) * PITCHD + 2 * b] = make_float2(v, v);
                }
            }
        }

        // copy 4 MLP rows of h into smem, transposed [k][r]
        for (int i = tid; i < 4 * HID; i += NTHR) {
            int r = i >> 9, k = i & (HID - 1);
            hbufS[k * 4 + r] = __ldcg(&hb[(size_t)(mrowb + r) * HID + k]);
        }
        __syncthreads();

        {   // layer 1: all 512 threads, 8-way k-split; thread=(ks,u1), 4 rows each
            int ks = tid >> 6, u1 = tid & 63;
            const float* wq = g_W1t + (size_t)(ks * 64) * 64 + u1;
            const float* hq = hbufS + ks * 64 * 4;
            float a0 = 0.f, a1 = 0.f, a2 = 0.f, a3 = 0.f;
#pragma unroll 4
            for (int kk = 0; kk < 64; kk++) {
                float w = __ldg(wq + (size_t)kk * 64);
                float4 hv = *(const float4*)(hq + kk * 4);   // broadcast LDS.128
                a0 = fmaf(hv.x, w, a0);
                a1 = fmaf(hv.y, w, a1);
                a2 = fmaf(hv.z, w, a2);
                a3 = fmaf(hv.w, w, a3);
            }
            float* pp = p1s + ks * 256 + u1;
            pp[0]   = a0;
            pp[64]  = a1;
            pp[128] = a2;
            pp[192] = a3;
        }
        __syncthreads();
        if (tid < 256) {  // layer 1 combine + relu
            int r = tid >> 6, u1 = tid & 63;
            float v = __ldg(&b1[u1]);
#pragma unroll
            for (int ks = 0; ks < 8; ks++) v += p1s[ks * 256 + r * 64 + u1];
            y1s[r * 64 + u1] = fmaxf(v, 0.f);
        }
        __syncthreads();
        if (tid < 64) {   // layer 2: 64 -> 16
            int r = tid >> 4, u2 = tid & 15;
            const float* yr = y1s + r * 64;
            float v = __ldg(&b2[u2]);
#pragma unroll
            for (int kk = 0; kk < 64; kk++)
                v = fmaf(yr[kk], __ldg(&g_W2t[kk * 16 + u2]), v);
            y2s[r * 16 + u2] = fmaxf(v, 0.f);
        }
        __syncthreads();
        if (tid < 8) {    // layer 3: 16 -> 2, write y + release
            int r = tid >> 1, j = tid & 1;
            const float* yr = y2s + r * 16;
            float v = __ldg(&b3[j]);
#pragma unroll
            for (int kk = 0; kk < 16; kk++) v = fmaf(yr[kk], __ldg(&W3[j * 16 + kk]), v);
            v = fmaxf(v, 0.f);
            int row = mrowb + r;
            __stcg(&g_y[row * 2 + j], v);
            out[(size_t)row * SEQ * 2 + (size_t)t * 2 + j] = v;
            __threadfence();                 // release y write
            atomicAdd(&g_ycnt[bt], 1u);      // 8 per block -> 64 per bt per step
        }

        __syncthreads();   // staging + MLP + red reads complete before next step
    }
}

extern "C" void kernel_launch(void* const* d_in, const int* in_sizes, int n_in,
                              void* d_out, int out_size) {
    const float* x      = (const float*)d_in[0];
    const float* pos    = (const float*)d_in[1];
    const float* hidden = (const float*)d_in[2];
    const float* cell   = (const float*)d_in[3];
    const float* W_ih   = (const float*)d_in[4];
    const float* W_hh   = (const float*)d_in[5];
    const float* b_ih   = (const float*)d_in[6];
    const float* b_hh   = (const float*)d_in[7];
    const float* W1     = (const float*)d_in[8];
    const float* b1     = (const float*)d_in[9];
    const float* W2     = (const float*)d_in[10];
    const float* b2     = (const float*)d_in[11];
    const float* W3     = (const float*)d_in[12];
    const float* b3     = (const float*)d_in[13];
    float* out = (float*)d_out;

    cudaFuncSetAttribute((const void*)lstm_persistent,
                         cudaFuncAttributeMaxDynamicSharedMemorySize, SMEM_BYTES);

    precompute_kernel<<<512, 256>>>(W_ih, W_hh, b_ih, b_hh, hidden, pos, W1, W2);
    lstm_persistent<<<NBLK, NTHR, SMEM_BYTES>>>(x, pos, cell, b1, b2, W3, b3, out);
}